// round 12
// baseline (speedup 1.0000x reference)
#include <cuda_runtime.h>
#include <cuda_bf16.h>

// ============================================================================
// ECE over N=2^24 samples, 15 bins — register-only hot loop.
//
// Identity:  x = c*nb,  d = c - a
//   U_k = sum_i d_i * [x_i > k],  k = 0..14    (15 register accumulators)
//   S_b = U_b - U_{b+1} (U_15 = 0);   ece = sum_{b<nb} |S_b| / n
// Self-gating: c<=0 / NaN fail every compare. Bit-exact vs ceil binning.
//
// R12 vs R10 (32.6us):
//  * __ldcv (volatile, no L2 allocate): every profile R2-R11 pins DRAM at
//    47-58% regardless of SM-side structure -> suspected L2-allocate miss
//    concurrency plateau (~4.5 TB/s). B300_MICROARCH measured its 6300 B/cyc
//    streaming ceiling with LDG.cv specifically.
//  * 15 DISTINCT predicate registers: all setps first, then all @p adds —
//    removes the single-pred in-order interlock, overlaps the 13-cyc
//    pred-as-guard latency across all 15 pairs.
// ============================================================================

#define TPB 256
#define NBINS 15
#define BSTRIDE 16
#define NBLOCKS 740          // 5 CTAs/SM * 148 SMs, exact single wave
#define MAX_BLOCKS 4096

__device__ float g_partial[MAX_BLOCKS * BSTRIDE];
__device__ unsigned int g_count = 0;

// x = c*nb, d = c - a. A[k] += d for every k in 0..14 with x > k.
// 15 independent setp->@p add pairs on 15 distinct predicate registers.
__device__ __forceinline__ void accum15(float x, float d, float* A) {
    asm("{\n\t"
        ".reg .pred p0,p1,p2,p3,p4,p5,p6,p7,p8,p9,p10,p11,p12,p13,p14;\n\t"
        "setp.gt.f32 p0,  %15, 0f00000000;\n\t"
        "setp.gt.f32 p1,  %15, 0f3F800000;\n\t"
        "setp.gt.f32 p2,  %15, 0f40000000;\n\t"
        "setp.gt.f32 p3,  %15, 0f40400000;\n\t"
        "setp.gt.f32 p4,  %15, 0f40800000;\n\t"
        "setp.gt.f32 p5,  %15, 0f40A00000;\n\t"
        "setp.gt.f32 p6,  %15, 0f40C00000;\n\t"
        "setp.gt.f32 p7,  %15, 0f40E00000;\n\t"
        "setp.gt.f32 p8,  %15, 0f41000000;\n\t"
        "setp.gt.f32 p9,  %15, 0f41100000;\n\t"
        "setp.gt.f32 p10, %15, 0f41200000;\n\t"
        "setp.gt.f32 p11, %15, 0f41300000;\n\t"
        "setp.gt.f32 p12, %15, 0f41400000;\n\t"
        "setp.gt.f32 p13, %15, 0f41500000;\n\t"
        "setp.gt.f32 p14, %15, 0f41600000;\n\t"
        "@p0  add.f32 %0,  %0,  %16;\n\t"
        "@p1  add.f32 %1,  %1,  %16;\n\t"
        "@p2  add.f32 %2,  %2,  %16;\n\t"
        "@p3  add.f32 %3,  %3,  %16;\n\t"
        "@p4  add.f32 %4,  %4,  %16;\n\t"
        "@p5  add.f32 %5,  %5,  %16;\n\t"
        "@p6  add.f32 %6,  %6,  %16;\n\t"
        "@p7  add.f32 %7,  %7,  %16;\n\t"
        "@p8  add.f32 %8,  %8,  %16;\n\t"
        "@p9  add.f32 %9,  %9,  %16;\n\t"
        "@p10 add.f32 %10, %10, %16;\n\t"
        "@p11 add.f32 %11, %11, %16;\n\t"
        "@p12 add.f32 %12, %12, %16;\n\t"
        "@p13 add.f32 %13, %13, %16;\n\t"
        "@p14 add.f32 %14, %14, %16;\n\t"
        "}"
        : "+f"(A[0]), "+f"(A[1]), "+f"(A[2]), "+f"(A[3]), "+f"(A[4]),
          "+f"(A[5]), "+f"(A[6]), "+f"(A[7]), "+f"(A[8]), "+f"(A[9]),
          "+f"(A[10]), "+f"(A[11]), "+f"(A[12]), "+f"(A[13]), "+f"(A[14])
        : "f"(x), "f"(d));
}

__global__ __launch_bounds__(TPB, 5)
void ece_kernel(const float* __restrict__ conf,
                const float* __restrict__ ac,
                const int* __restrict__ num_bins_p,
                int n,
                float* __restrict__ out) {
    const int tid = threadIdx.x;
    const int nb = *num_bins_p;          // valid for nb <= 15
    const float fnb = (float)nb;

    float A[NBINS];
    #pragma unroll
    for (int k = 0; k < NBINS; k++) A[k] = 0.0f;

    const int nvec = n >> 2;
    const float4* __restrict__ c4 = (const float4*)conf;
    const float4* __restrict__ a4 = (const float4*)ac;
    const int S = gridDim.x * blockDim.x;

    int i = blockIdx.x * blockDim.x + tid;
    // 2x unrolled grid-stride, 4 front-batched LDG.128.CV (no L2 allocate)
    for (; i + S < nvec; i += 2 * S) {
        const float4 c0 = __ldcv(&c4[i]);
        const float4 c1 = __ldcv(&c4[i + S]);
        const float4 a0 = __ldcv(&a4[i]);
        const float4 a1 = __ldcv(&a4[i + S]);
        accum15(c0.x * fnb, c0.x - a0.x, A);
        accum15(c0.y * fnb, c0.y - a0.y, A);
        accum15(c0.z * fnb, c0.z - a0.z, A);
        accum15(c0.w * fnb, c0.w - a0.w, A);
        accum15(c1.x * fnb, c1.x - a1.x, A);
        accum15(c1.y * fnb, c1.y - a1.y, A);
        accum15(c1.z * fnb, c1.z - a1.z, A);
        accum15(c1.w * fnb, c1.w - a1.w, A);
    }
    for (; i < nvec; i += S) {
        const float4 c = __ldcv(&c4[i]);
        const float4 a = __ldcv(&a4[i]);
        accum15(c.x * fnb, c.x - a.x, A);
        accum15(c.y * fnb, c.y - a.y, A);
        accum15(c.z * fnb, c.z - a.z, A);
        accum15(c.w * fnb, c.w - a.w, A);
    }
    // scalar remainder (n not multiple of 4): block 0 only
    if (blockIdx.x == 0) {
        for (int j = (nvec << 2) + tid; j < n; j += blockDim.x) {
            const float cf = conf[j];
            accum15(cf * fnb, cf - ac[j], A);
        }
    }

    // ---- block reduction of the 15 per-thread U_k (one-shot) ----
    __shared__ float red[NBINS * TPB];   // 15 KB
    #pragma unroll
    for (int k = 0; k < NBINS; k++)
        red[k * TPB + tid] = A[k];
    __syncthreads();

    for (int s = TPB / 2; s > 0; s >>= 1) {
        if (tid < s) {
            #pragma unroll
            for (int k = 0; k < NBINS; k++)
                red[k * TPB + tid] += red[k * TPB + tid + s];
        }
        __syncthreads();
    }

    if (tid < BSTRIDE)
        g_partial[blockIdx.x * BSTRIDE + tid] =
            (tid < NBINS) ? red[tid * TPB] : 0.0f;   // slot 15 = U_15 = 0

    // ---- last-block tail reduction (no second launch) ----
    __shared__ bool is_last;
    __threadfence();
    if (tid == 0) {
        unsigned int ticket = atomicAdd(&g_count, 1u);
        is_last = (ticket == gridDim.x - 1);
    }
    __syncthreads();

    if (is_last) {
        __threadfence();
        const int total = gridDim.x * BSTRIDE;
        float s = 0.0f;
        for (int e = tid; e < total; e += TPB)
            s += g_partial[e];

        __shared__ float r2[TPB];
        r2[tid] = s;
        __syncthreads();

        __shared__ float U[BSTRIDE];
        if (tid < BSTRIDE) {
            float t = 0.0f;
            #pragma unroll
            for (int k = 0; k < TPB / BSTRIDE; k++)
                t += r2[tid + k * BSTRIDE];
            U[tid] = t;                       // U[15] = 0 automatically
        }
        __syncthreads();

        if (tid == 0) {
            float tot = 0.0f;
            for (int b = 0; b < nb; b++)      // S_b = U_b - U_{b+1}
                tot += fabsf(U[b] - U[b + 1]);
            out[0] = tot / (float)n;
            g_count = 0;                      // reset for next graph replay
        }
    }
}

extern "C" void kernel_launch(void* const* d_in, const int* in_sizes, int n_in,
                              void* d_out, int out_size) {
    const float* conf = (const float*)d_in[0];
    const float* acc  = (const float*)d_in[1];
    const int*   nbp  = (const int*)d_in[2];
    float* out = (float*)d_out;
    const int n = in_sizes[0];

    int nvec = n >> 2;
    int blocks = (nvec + TPB - 1) / TPB;
    if (blocks > NBLOCKS) blocks = NBLOCKS;
    if (blocks < 1) blocks = 1;

    ece_kernel<<<blocks, TPB>>>(conf, acc, nbp, n, out);
}

// round 13
// speedup vs baseline: 1.1405x; 1.1405x over previous
#include <cuda_runtime.h>
#include <cuda_bf16.h>

// ============================================================================
// ECE over N=2^24 samples, 15 bins — HYBRID kernel: two structural families
// run concurrently on disjoint halves of the data, stressing disjoint pipes.
//
//   blocks [0, 370):   shared-memory histogram (LSU/shared-pipe bound,
//                      ~25% issue standalone)   -> elements [0, N/2)
//   blocks [370, 740): register threshold accumulators (fma/alu bound,
//                      ~60% issue standalone)   -> elements [N/2, N)
//
// Each family alone plateaus at ~4.2-4.5 TB/s (R2-R12). Their bottleneck
// resources are disjoint, and 740 = 5 CTAs/SM exactly, so the bid->SM LUT
// gives every SM ~2.5 CTAs of each family -> both rates add.
//
// Both families write SIGNED per-block bin sums S_b (b<15) to g_partial;
// threshold blocks difference U_k -> S_b = U_b - U_{b+1} locally.
// Fused last-block tail does sum_b |sum_blocks S_b| / n.
//
// Binning (both paths bit-exact vs reference):
//   histogram: b = umin((unsigned)(f2i_ru(c*nb)-1), 15); bins >= nb dropped
//   threshold: U_k = sum d*[c*nb > k] (self-gating, ceil-exact compares)
// ============================================================================

#define TPB 256
#define MAX_BINS 16
#define NBINS 15
#define NBLOCKS 740          // 5 CTAs/SM * 148 SMs exact
#define HBLOCKS 370          // histogram family size
#define MAX_BLOCKS 4096

__device__ float g_partial[MAX_BLOCKS * MAX_BINS];
__device__ unsigned int g_count = 0;

// --- histogram family: lean branchless shared bin update -------------------
__device__ __forceinline__ void bin_add(float* __restrict__ sb, int tid,
                                        float cf, float af, float fnb) {
    unsigned int b = umin((unsigned int)(__float2int_ru(cf * fnb) - 1),
                          (unsigned int)(MAX_BINS - 1));
    sb[b * TPB + tid] += cf - af;
}

// --- threshold family: 15 setp -> @p add pairs on distinct preds ------------
__device__ __forceinline__ void accum15(float x, float d, float* A) {
    asm("{\n\t"
        ".reg .pred p0,p1,p2,p3,p4,p5,p6,p7,p8,p9,p10,p11,p12,p13,p14;\n\t"
        "setp.gt.f32 p0,  %15, 0f00000000;\n\t"
        "setp.gt.f32 p1,  %15, 0f3F800000;\n\t"
        "setp.gt.f32 p2,  %15, 0f40000000;\n\t"
        "setp.gt.f32 p3,  %15, 0f40400000;\n\t"
        "setp.gt.f32 p4,  %15, 0f40800000;\n\t"
        "setp.gt.f32 p5,  %15, 0f40A00000;\n\t"
        "setp.gt.f32 p6,  %15, 0f40C00000;\n\t"
        "setp.gt.f32 p7,  %15, 0f40E00000;\n\t"
        "setp.gt.f32 p8,  %15, 0f41000000;\n\t"
        "setp.gt.f32 p9,  %15, 0f41100000;\n\t"
        "setp.gt.f32 p10, %15, 0f41200000;\n\t"
        "setp.gt.f32 p11, %15, 0f41300000;\n\t"
        "setp.gt.f32 p12, %15, 0f41400000;\n\t"
        "setp.gt.f32 p13, %15, 0f41500000;\n\t"
        "setp.gt.f32 p14, %15, 0f41600000;\n\t"
        "@p0  add.f32 %0,  %0,  %16;\n\t"
        "@p1  add.f32 %1,  %1,  %16;\n\t"
        "@p2  add.f32 %2,  %2,  %16;\n\t"
        "@p3  add.f32 %3,  %3,  %16;\n\t"
        "@p4  add.f32 %4,  %4,  %16;\n\t"
        "@p5  add.f32 %5,  %5,  %16;\n\t"
        "@p6  add.f32 %6,  %6,  %16;\n\t"
        "@p7  add.f32 %7,  %7,  %16;\n\t"
        "@p8  add.f32 %8,  %8,  %16;\n\t"
        "@p9  add.f32 %9,  %9,  %16;\n\t"
        "@p10 add.f32 %10, %10, %16;\n\t"
        "@p11 add.f32 %11, %11, %16;\n\t"
        "@p12 add.f32 %12, %12, %16;\n\t"
        "@p13 add.f32 %13, %13, %16;\n\t"
        "@p14 add.f32 %14, %14, %16;\n\t"
        "}"
        : "+f"(A[0]), "+f"(A[1]), "+f"(A[2]), "+f"(A[3]), "+f"(A[4]),
          "+f"(A[5]), "+f"(A[6]), "+f"(A[7]), "+f"(A[8]), "+f"(A[9]),
          "+f"(A[10]), "+f"(A[11]), "+f"(A[12]), "+f"(A[13]), "+f"(A[14])
        : "f"(x), "f"(d));
}

__global__ __launch_bounds__(TPB, 5)
void ece_kernel(const float* __restrict__ conf,
                const float* __restrict__ ac,
                const int* __restrict__ num_bins_p,
                int n,
                float* __restrict__ out) {
    __shared__ float smem[MAX_BINS * TPB];   // 16 KB, used by both paths
    const int tid = threadIdx.x;
    const int nb = *num_bins_p;              // valid for nb <= 15
    const float fnb = (float)nb;

    const int nvec = n >> 2;
    const int half = nvec >> 1;              // family data split point
    const float4* __restrict__ c4 = (const float4*)conf;
    const float4* __restrict__ a4 = (const float4*)ac;

    if (blockIdx.x < HBLOCKS) {
        // ============ HISTOGRAM FAMILY: elements [0, half) =================
        #pragma unroll
        for (int b = 0; b < MAX_BINS; b++)
            smem[b * TPB + tid] = 0.0f;
        __syncthreads();

        const int S = HBLOCKS * TPB;
        int i = blockIdx.x * TPB + tid;
        for (; i + 3 * S < half; i += 4 * S) {
            const float4 c0 = __ldcs(&c4[i]);
            const float4 c1 = __ldcs(&c4[i + S]);
            const float4 c2 = __ldcs(&c4[i + 2 * S]);
            const float4 c3 = __ldcs(&c4[i + 3 * S]);
            const float4 a0 = __ldcs(&a4[i]);
            const float4 a1 = __ldcs(&a4[i + S]);
            const float4 a2 = __ldcs(&a4[i + 2 * S]);
            const float4 a3 = __ldcs(&a4[i + 3 * S]);
            bin_add(smem, tid, c0.x, a0.x, fnb);
            bin_add(smem, tid, c0.y, a0.y, fnb);
            bin_add(smem, tid, c0.z, a0.z, fnb);
            bin_add(smem, tid, c0.w, a0.w, fnb);
            bin_add(smem, tid, c1.x, a1.x, fnb);
            bin_add(smem, tid, c1.y, a1.y, fnb);
            bin_add(smem, tid, c1.z, a1.z, fnb);
            bin_add(smem, tid, c1.w, a1.w, fnb);
            bin_add(smem, tid, c2.x, a2.x, fnb);
            bin_add(smem, tid, c2.y, a2.y, fnb);
            bin_add(smem, tid, c2.z, a2.z, fnb);
            bin_add(smem, tid, c2.w, a2.w, fnb);
            bin_add(smem, tid, c3.x, a3.x, fnb);
            bin_add(smem, tid, c3.y, a3.y, fnb);
            bin_add(smem, tid, c3.z, a3.z, fnb);
            bin_add(smem, tid, c3.w, a3.w, fnb);
        }
        for (; i < half; i += S) {
            const float4 c = __ldcs(&c4[i]);
            const float4 a = __ldcs(&a4[i]);
            bin_add(smem, tid, c.x, a.x, fnb);
            bin_add(smem, tid, c.y, a.y, fnb);
            bin_add(smem, tid, c.z, a.z, fnb);
            bin_add(smem, tid, c.w, a.w, fnb);
        }
        if (blockIdx.x == 0) {   // scalar remainder (n not multiple of 4)
            for (int j = (nvec << 2) + tid; j < n; j += TPB)
                bin_add(smem, tid, conf[j], ac[j], fnb);
        }
        __syncthreads();

        for (int s = TPB / 2; s > 0; s >>= 1) {
            if (tid < s) {
                #pragma unroll
                for (int b = 0; b < MAX_BINS; b++)
                    smem[b * TPB + tid] += smem[b * TPB + tid + s];
            }
            __syncthreads();
        }
        if (tid < MAX_BINS)
            g_partial[blockIdx.x * MAX_BINS + tid] =
                (tid < nb) ? smem[tid * TPB] : 0.0f;   // drop overflow bins
    } else {
        // ============ THRESHOLD FAMILY: elements [half, nvec) ==============
        float A[NBINS];
        #pragma unroll
        for (int k = 0; k < NBINS; k++) A[k] = 0.0f;

        const int S = (NBLOCKS - HBLOCKS) * TPB;
        int i = half + (blockIdx.x - HBLOCKS) * TPB + tid;
        for (; i + S < nvec; i += 2 * S) {
            const float4 c0 = __ldcs(&c4[i]);
            const float4 c1 = __ldcs(&c4[i + S]);
            const float4 a0 = __ldcs(&a4[i]);
            const float4 a1 = __ldcs(&a4[i + S]);
            accum15(c0.x * fnb, c0.x - a0.x, A);
            accum15(c0.y * fnb, c0.y - a0.y, A);
            accum15(c0.z * fnb, c0.z - a0.z, A);
            accum15(c0.w * fnb, c0.w - a0.w, A);
            accum15(c1.x * fnb, c1.x - a1.x, A);
            accum15(c1.y * fnb, c1.y - a1.y, A);
            accum15(c1.z * fnb, c1.z - a1.z, A);
            accum15(c1.w * fnb, c1.w - a1.w, A);
        }
        for (; i < nvec; i += S) {
            const float4 c = __ldcs(&c4[i]);
            const float4 a = __ldcs(&a4[i]);
            accum15(c.x * fnb, c.x - a.x, A);
            accum15(c.y * fnb, c.y - a.y, A);
            accum15(c.z * fnb, c.z - a.z, A);
            accum15(c.w * fnb, c.w - a.w, A);
        }

        #pragma unroll
        for (int k = 0; k < NBINS; k++)
            smem[k * TPB + tid] = A[k];
        __syncthreads();

        for (int s = TPB / 2; s > 0; s >>= 1) {
            if (tid < s) {
                #pragma unroll
                for (int k = 0; k < NBINS; k++)
                    smem[k * TPB + tid] += smem[k * TPB + tid + s];
            }
            __syncthreads();
        }
        if (tid < MAX_BINS) {
            // S_b = U_b - U_{b+1}, U_15 = 0; slots >= nb written as 0
            float Ub  = (tid < NBINS) ? smem[tid * TPB] : 0.0f;
            float Ub1 = (tid + 1 < NBINS) ? smem[(tid + 1) * TPB] : 0.0f;
            g_partial[blockIdx.x * MAX_BINS + tid] =
                (tid < nb) ? (Ub - Ub1) : 0.0f;
        }
    }

    // ---- last-block tail reduction (shared by both families) ----
    __shared__ bool is_last;
    __threadfence();
    if (tid == 0) {
        unsigned int ticket = atomicAdd(&g_count, 1u);
        is_last = (ticket == gridDim.x - 1);
    }
    __syncthreads();

    if (is_last) {
        __threadfence();
        const int total = gridDim.x * MAX_BINS;
        float s = 0.0f;
        for (int e = tid; e < total; e += TPB)   // slot = e & 15 fixed per thread
            s += g_partial[e];

        __shared__ float r2[TPB];
        r2[tid] = s;
        __syncthreads();

        if (tid < MAX_BINS) {
            float t = 0.0f;
            #pragma unroll
            for (int k = 0; k < TPB / MAX_BINS; k++)
                t += r2[tid + k * MAX_BINS];
            r2[tid] = fabsf(t);                  // |sum_blocks S_b|
        }
        __syncthreads();

        if (tid == 0) {
            float tot = 0.0f;
            for (int b = 0; b < nb; b++)
                tot += r2[b];
            out[0] = tot / (float)n;
            g_count = 0;                         // reset for next graph replay
        }
    }
}

extern "C" void kernel_launch(void* const* d_in, const int* in_sizes, int n_in,
                              void* d_out, int out_size) {
    const float* conf = (const float*)d_in[0];
    const float* acc  = (const float*)d_in[1];
    const int*   nbp  = (const int*)d_in[2];
    float* out = (float*)d_out;
    const int n = in_sizes[0];

    // fixed grid: family split assumes NBLOCKS; empty blocks still write 0
    ece_kernel<<<NBLOCKS, TPB>>>(conf, acc, nbp, n, out);
}